// round 2
// baseline (speedup 1.0000x reference)
#include <cuda_runtime.h>

#define NBLK 128
#define NTHR 256
#define GSZ (NBLK * NTHR)
#define SMEM_FLOATS (12800 + NTHR)
#define SMEM_BYTES (SMEM_FLOATS * 4)

struct P {
  const float *x, *w1, *w2;
  const float *bn1g, *bn1b, *bn2g, *bn2b;
  const float *wc1, *bc1, *bn3g, *bn3b;
  const float *wc2, *bc2, *bn4g, *bn4b;
  const float *wc3, *bc3, *bn5g, *bn5b;
  const float *wf1, *bf1, *wf2, *bf2;
  float *out;
};

// ---- persistent-kernel scratch (device globals; no allocation) ----
__device__ unsigned int g_cnt = 0;
__device__ volatile unsigned int g_gen = 0;

__device__ float g_xs[131072];     // standardized inputs / pooled feats
__device__ float g_drive[131072];  // LCA input drive / pooled feats
__device__ float g_u[131072];      // LCA membrane potential
__device__ float g_recon[165888];  // factored-inhibition partial recons [NPART][4][C][36][36]
__device__ float g_h[131072];      // activations
__device__ float g_m[256];         // per-sample / per-channel mean
__device__ float g_rs[256];        // per-sample / per-channel inv-std
__device__ float g_fc[2048];       // fc1 output

// ---- software grid barrier (all 128 blocks co-resident on >=148 SMs) ----
// Reader-side __threadfence() emits CCTL.IVALL on sm_103a -> invalidates L1D,
// so normal loads after the barrier observe other blocks' writes.
__device__ __forceinline__ void grid_sync() {
  __syncthreads();
  if (threadIdx.x == 0) {
    unsigned int gen = g_gen;
    __threadfence();  // release: make my block's writes globally visible
    if (atomicAdd(&g_cnt, 1u) == (unsigned)(NBLK - 1)) {
      g_cnt = 0u;
      __threadfence();
      g_gen = gen + 1u;
    } else {
      while (g_gen == gen) { __nanosleep(64); }
      __threadfence();  // acquire: L1D invalidate before reading shared data
    }
  }
  __syncthreads();
}

__device__ __forceinline__ float block_reduce(float v, float *red) {
  red[threadIdx.x] = v;
  __syncthreads();
#pragma unroll
  for (int s = NTHR / 2; s > 0; s >>= 1) {
    if (threadIdx.x < s) red[threadIdx.x] += red[threadIdx.x + s];
    __syncthreads();
  }
  float r = red[0];
  __syncthreads();
  return r;
}

__device__ void zero_buf(float *b, int n) {
  for (int i = blockIdx.x * NTHR + threadIdx.x; i < n; i += GSZ) b[i] = 0.f;
}

// per-sample mean / 1/(std+1e-8) over `len` elements (B=4)
__device__ void sample_stats(const float *in, int len, float *red) {
  for (int n = blockIdx.x; n < 4; n += NBLK) {
    const float *p = in + n * len;
    float s = 0.f, ss = 0.f;
    for (int i = threadIdx.x; i < len; i += NTHR) {
      float v = p[i];
      s += v;
      ss += v * v;
    }
    s = block_reduce(s, red);
    ss = block_reduce(ss, red);
    if (threadIdx.x == 0) {
      float m = s / (float)len;
      float var = fmaxf(ss / (float)len - m * m, 0.f);
      g_m[n] = m;
      g_rs[n] = 1.f / (sqrtf(var) + 1e-8f);
    }
    __syncthreads();
  }
}

__device__ void standardize(const float *in, float *out, int len) {
  for (int i = blockIdx.x * NTHR + threadIdx.x; i < 4 * len; i += GSZ) {
    int n = i / len;
    out[i] = (in[i] - g_m[n]) * g_rs[n];
  }
}

// generic 5x5 "same" conv (cross-correlation), optional bias+relu. NCHW, B=4.
__device__ void conv5x5(const float *__restrict__ in, const float *__restrict__ w,
                        const float *__restrict__ bias, float *__restrict__ out,
                        int Cin, int Cout, int HW, bool do_relu) {
  int npix = HW * HW;
  int N = 4 * Cout * npix;
  for (int idx = blockIdx.x * NTHR + threadIdx.x; idx < N; idx += GSZ) {
    int x = idx % HW;
    int t = idx / HW;
    int y = t % HW;
    t /= HW;
    int f = t % Cout;
    int n = t / Cout;
    float acc = bias ? bias[f] : 0.f;
    const float *wb = w + f * Cin * 25;
    for (int c = 0; c < Cin; ++c) {
      const float *ib = in + (n * Cin + c) * npix;
      const float *wc = wb + c * 25;
#pragma unroll
      for (int ky = 0; ky < 5; ++ky) {
        int yy = y + ky - 2;
        if ((unsigned)yy >= (unsigned)HW) continue;
#pragma unroll
        for (int kx = 0; kx < 5; ++kx) {
          int xx = x + kx - 2;
          if ((unsigned)xx >= (unsigned)HW) continue;
          acc += ib[yy * HW + xx] * wc[ky * 5 + kx];
        }
      }
    }
    out[idx] = do_relu ? fmaxf(acc, 0.f) : acc;
  }
}

__device__ void maxpool2(const float *__restrict__ in, float *__restrict__ out,
                         int C, int H) {
  int Ho = H / 2;
  int N = 4 * C * Ho * Ho;
  for (int idx = blockIdx.x * NTHR + threadIdx.x; idx < N; idx += GSZ) {
    int xo = idx % Ho;
    int t = idx / Ho;
    int yo = t % Ho;
    t /= Ho;  // t = n*C + c
    const float *ib = in + t * H * H + (yo * 2) * H + xo * 2;
    out[idx] = fmaxf(fmaxf(ib[0], ib[1]), fmaxf(ib[H], ib[H + 1]));
  }
}

// BatchNorm batch statistics over (N,H,W) per channel (training-mode math)
__device__ void bn_stats(const float *in, int C, int npix, float *red) {
  int cnt = 4 * npix;
  for (int c = blockIdx.x; c < C; c += NBLK) {
    float s = 0.f, ss = 0.f;
    for (int i = threadIdx.x; i < cnt; i += NTHR) {
      int n = i / npix, pp = i % npix;
      float v = in[(n * C + c) * npix + pp];
      s += v;
      ss += v * v;
    }
    s = block_reduce(s, red);
    ss = block_reduce(ss, red);
    if (threadIdx.x == 0) {
      float m = s / (float)cnt;
      float var = fmaxf(ss / (float)cnt - m * m, 0.f);
      g_m[c] = m;
      g_rs[c] = rsqrtf(var + 1e-5f);
    }
    __syncthreads();
  }
}

__device__ void bn_apply(float *buf, int C, int npix, const float *gam, const float *bet) {
  int N = 4 * C * npix;
  for (int i = blockIdx.x * NTHR + threadIdx.x; i < N; i += GSZ) {
    int c = (i / npix) % C;
    buf[i] = (buf[i] - g_m[c]) * g_rs[c] * gam[c] + bet[c];
  }
}

__device__ void relu_shift(const float *u, float *out, int n) {
  for (int i = blockIdx.x * NTHR + threadIdx.x; i < n; i += GSZ)
    out[i] = fmaxf(u[i] - 0.5f, 0.f);
}

// ===================== factored LCA iteration =====================
// inhib = conv(a, G), G = W * W (Gram), factored exactly as:
//   recon_ext[n,c,Y,X] = sum_{f,ky,kx} w[f,c,ky,kx] * a[n,f,Y-ky,X-kx]   (Y,X in [0,36))
//   inhib[n,f,y,x]     = sum_{c,ky,kx} w[f,c,ky,kx] * recon_ext[n,c,y+ky,x+kx]
// a = relu(u - 0.5) computed on the fly. F split into NPART partial recons
// for thread-level parallelism; phase B sums the partials.

template <int F, int C, int NPART>
__device__ void lca_phaseA(const float *__restrict__ u, float *__restrict__ recon,
                           const float *__restrict__ sw) {
  constexpr int FP = F / NPART;
  const int NJOB = NPART * 4 * 1296;
  for (int idx = blockIdx.x * NTHR + threadIdx.x; idx < NJOB; idx += GSZ) {
    int pix = idx % 1296;
    int t = idx / 1296;  // part*4 + n
    int n = t & 3;
    int part = t >> 2;
    int Y = pix / 36, X = pix % 36;
    float acc[C];
#pragma unroll
    for (int c = 0; c < C; ++c) acc[c] = 0.f;
    for (int ff = 0; ff < FP; ++ff) {
      int f = part * FP + ff;
      const float *ub = u + (n * F + f) * 1024;
      const float *wf = sw + f * C * 25;
#pragma unroll
      for (int ky = 0; ky < 5; ++ky) {
        int y = Y - ky;
        if ((unsigned)y >= 32u) continue;
#pragma unroll
        for (int kx = 0; kx < 5; ++kx) {
          int x = X - kx;
          if ((unsigned)x >= 32u) continue;
          float a = fmaxf(ub[y * 32 + x] - 0.5f, 0.f);
#pragma unroll
          for (int c = 0; c < C; ++c) acc[c] += a * wf[c * 25 + ky * 5 + kx];
        }
      }
    }
    float *rb = recon + t * C * 1296 + pix;
#pragma unroll
    for (int c = 0; c < C; ++c) rb[c * 1296] = acc[c];
  }
}

template <int F, int C, int FG>  // NPART fixed at 2
__device__ void lca_phaseB(float *__restrict__ u, const float *__restrict__ recon,
                           const float *__restrict__ drive, const float *__restrict__ sw) {
  constexpr int NG = F / FG;
  const int NJOB = 4 * NG * 1024;
  for (int idx = blockIdx.x * NTHR + threadIdx.x; idx < NJOB; idx += GSZ) {
    int pix = idx % 1024;
    int t = idx / 1024;  // n*NG + g
    int g = t % NG;
    int n = t / NG;
    int y = pix >> 5, x = pix & 31;
    float acc[FG];
#pragma unroll
    for (int j = 0; j < FG; ++j) acc[j] = 0.f;
    for (int c = 0; c < C; ++c) {
      const float *rb0 = recon + (n * C + c) * 1296;
      const float *rb1 = recon + ((4 + n) * C + c) * 1296;
      const float *wc = sw + (g * FG * C + c) * 25;
#pragma unroll
      for (int ky = 0; ky < 5; ++ky) {
        int off = (y + ky) * 36 + x;
#pragma unroll
        for (int kx = 0; kx < 5; ++kx) {
          float rv = rb0[off + kx] + rb1[off + kx];
          const float *wp = wc + ky * 5 + kx;
#pragma unroll
          for (int j = 0; j < FG; ++j) acc[j] += rv * wp[j * C * 25];
        }
      }
    }
#pragma unroll
    for (int j = 0; j < FG; ++j) {
      int f = g * FG + j;
      int i = (n * F + f) * 1024 + pix;
      float uv = u[i];
      float a = fmaxf(uv - 0.5f, 0.f);
      u[i] = uv + 0.001f * (drive[i] - uv - acc[j] + a);
    }
  }
}

__device__ void fc(const float *__restrict__ in, const float *__restrict__ w,
                   const float *__restrict__ bias, float *__restrict__ out,
                   int K, int J, bool do_relu) {
  int N = 4 * J;
  for (int idx = blockIdx.x * NTHR + threadIdx.x; idx < N; idx += GSZ) {
    int j = idx % J, n = idx / J;
    float acc = bias[j];
    const float *wr = w + j * K;
    const float *ir = in + n * K;
    for (int k = 0; k < K; ++k) acc += ir[k] * wr[k];
    out[idx] = do_relu ? fmaxf(acc, 0.f) : acc;
  }
}

// ===================== the whole network, one persistent kernel =====================
__global__ void __launch_bounds__(NTHR, 1) splitnn_kernel(P p) {
  extern __shared__ float smem[];
  float *sw = smem;            // 12800 floats: LCA dictionary
  float *red = smem + 12800;   // 256 floats: reduction scratch

  // ---- standardize input, drive1, u=0 ----
  sample_stats(p.x, 3072, red);
  grid_sync();
  standardize(p.x, g_xs, 3072);
  zero_buf(g_u, 65536);
  grid_sync();
  conv5x5(g_xs, p.w1, nullptr, g_drive, 3, 16, 32, false);
  for (int i = threadIdx.x; i < 16 * 3 * 25; i += NTHR) sw[i] = p.w1[i];
  grid_sync();

  // ---- LCA1: F=16, C=3, 500 iters ----
  for (int it = 0; it < 500; ++it) {
    lca_phaseA<16, 3, 2>(g_u, g_recon, sw);
    grid_sync();
    lca_phaseB<16, 3, 8>(g_u, g_recon, g_drive, sw);
    grid_sync();
  }
  relu_shift(g_u, g_h, 65536);
  grid_sync();
  bn_stats(g_h, 16, 1024, red);
  grid_sync();
  bn_apply(g_h, 16, 1024, p.bn1g, p.bn1b);
  grid_sync();

  // ---- standardize, drive2, u=0 ----
  sample_stats(g_h, 16384, red);
  grid_sync();
  standardize(g_h, g_xs, 16384);
  zero_buf(g_u, 131072);
  grid_sync();
  conv5x5(g_xs, p.w2, nullptr, g_drive, 16, 32, 32, false);
  for (int i = threadIdx.x; i < 32 * 16 * 25; i += NTHR) sw[i] = p.w2[i];
  grid_sync();

  // ---- LCA2: F=32, C=16, 500 iters ----
  for (int it = 0; it < 500; ++it) {
    lca_phaseA<32, 16, 2>(g_u, g_recon, sw);
    grid_sync();
    lca_phaseB<32, 16, 8>(g_u, g_recon, g_drive, sw);
    grid_sync();
  }
  relu_shift(g_u, g_h, 131072);
  grid_sync();
  maxpool2(g_h, g_xs, 32, 32);  // -> [4,32,16,16]
  grid_sync();
  bn_stats(g_xs, 32, 256, red);
  grid_sync();
  bn_apply(g_xs, 32, 256, p.bn2g, p.bn2b);
  grid_sync();

  // ---- conv tail ----
  conv5x5(g_xs, p.wc1, p.bc1, g_h, 32, 64, 16, true);
  grid_sync();
  maxpool2(g_h, g_drive, 64, 16);  // -> [4,64,8,8]
  grid_sync();
  bn_stats(g_drive, 64, 64, red);
  grid_sync();
  bn_apply(g_drive, 64, 64, p.bn3g, p.bn3b);
  grid_sync();
  conv5x5(g_drive, p.wc2, p.bc2, g_h, 64, 128, 8, true);
  grid_sync();
  maxpool2(g_h, g_xs, 128, 8);  // -> [4,128,4,4]
  grid_sync();
  bn_stats(g_xs, 128, 16, red);
  grid_sync();
  bn_apply(g_xs, 128, 16, p.bn4g, p.bn4b);
  grid_sync();
  conv5x5(g_xs, p.wc3, p.bc3, g_h, 128, 256, 4, true);
  grid_sync();
  maxpool2(g_h, g_drive, 256, 4);  // -> [4,256,2,2] == flat [4,1024]
  grid_sync();
  bn_stats(g_drive, 256, 4, red);
  grid_sync();
  bn_apply(g_drive, 256, 4, p.bn5g, p.bn5b);
  grid_sync();

  // ---- classifier ----
  fc(g_drive, p.wf1, p.bf1, g_fc, 1024, 512, true);
  grid_sync();
  fc(g_fc, p.wf2, p.bf2, p.out, 512, 10, false);
}

extern "C" void kernel_launch(void *const *d_in, const int *in_sizes, int n_in,
                              void *d_out, int out_size) {
  (void)in_sizes;
  (void)n_in;
  (void)out_size;
  P p;
  p.x = (const float *)d_in[0];
  p.w1 = (const float *)d_in[1];
  p.w2 = (const float *)d_in[2];
  p.bn1g = (const float *)d_in[3];
  p.bn1b = (const float *)d_in[4];
  p.bn2g = (const float *)d_in[5];
  p.bn2b = (const float *)d_in[6];
  p.wc1 = (const float *)d_in[7];
  p.bc1 = (const float *)d_in[8];
  p.bn3g = (const float *)d_in[9];
  p.bn3b = (const float *)d_in[10];
  p.wc2 = (const float *)d_in[11];
  p.bc2 = (const float *)d_in[12];
  p.bn4g = (const float *)d_in[13];
  p.bn4b = (const float *)d_in[14];
  p.wc3 = (const float *)d_in[15];
  p.bc3 = (const float *)d_in[16];
  p.bn5g = (const float *)d_in[17];
  p.bn5b = (const float *)d_in[18];
  p.wf1 = (const float *)d_in[19];
  p.bf1 = (const float *)d_in[20];
  p.wf2 = (const float *)d_in[21];
  p.bf2 = (const float *)d_in[22];
  p.out = (float *)d_out;

  cudaFuncSetAttribute(reinterpret_cast<const void *>(splitnn_kernel),
                       cudaFuncAttributeMaxDynamicSharedMemorySize, SMEM_BYTES);
  splitnn_kernel<<<NBLK, NTHR, SMEM_BYTES>>>(p);
}

// round 3
// speedup vs baseline: 1.2816x; 1.2816x over previous
#include <cuda_runtime.h>

#define NBLK 148
#define NTHR 256
#define GSZ (NBLK * NTHR)

// smem layout (floats)
#define SW_A 0        // 12800: phaseA weights [f][tap][c]
#define SW_B 12800    // 12800: phaseB weights [c][tap][f]
#define RED_OFF 25600 // 256: reduction scratch
#define SMEM_FLOATS 25856
#define SMEM_BYTES (SMEM_FLOATS * 4)

struct P {
  const float *x, *w1, *w2;
  const float *bn1g, *bn1b, *bn2g, *bn2b;
  const float *wc1, *bc1, *bn3g, *bn3b;
  const float *wc2, *bc2, *bn4g, *bn4b;
  const float *wc3, *bc3, *bn5g, *bn5b;
  const float *wf1, *bf1, *wf2, *bf2;
  float *out;
};

// ---- persistent-kernel scratch (device globals; no allocation) ----
__device__ unsigned int g_cnt = 0;
__device__ volatile unsigned int g_gen = 0;

__device__ float g_xs[131072];     // standardized inputs / pooled feats
__device__ float g_drive[131072];  // LCA input drive / pooled feats
__device__ float g_u[131072];      // LCA membrane potential
__device__ float g_a[131072];      // LCA code a = relu(u - lambda)
__device__ float g_recon[165888];  // factored-inhibition recon
__device__ float g_h[131072];      // activations
__device__ float g_m[256];
__device__ float g_rs[256];
__device__ float g_fc[2048];

// each block gets a contiguous chunk of jobs -> all SMs active, coalesced
#define CHUNK_LOOP(NJOB)                                                   \
  const int _ck = ((NJOB) + NBLK - 1) / NBLK;                              \
  const int _j0 = blockIdx.x * _ck;                                        \
  const int _j1 = (_j0 + _ck < (NJOB)) ? (_j0 + _ck) : (NJOB);             \
  for (int idx = _j0 + (int)threadIdx.x; idx < _j1; idx += NTHR)

// ---- software grid barrier (148 blocks, 1 per SM, co-resident) ----
__device__ __forceinline__ void grid_sync() {
  __syncthreads();
  if (threadIdx.x == 0) {
    unsigned int gen = g_gen;
    __threadfence();  // release
    if (atomicAdd(&g_cnt, 1u) == (unsigned)(NBLK - 1)) {
      g_cnt = 0u;
      __threadfence();
      g_gen = gen + 1u;
    } else {
      while (g_gen == gen) { __nanosleep(64); }
      __threadfence();  // acquire (CCTL.IVALL -> drop stale L1)
    }
  }
  __syncthreads();
}

__device__ __forceinline__ float block_reduce(float v, float *red) {
  red[threadIdx.x] = v;
  __syncthreads();
#pragma unroll
  for (int s = NTHR / 2; s > 0; s >>= 1) {
    if (threadIdx.x < s) red[threadIdx.x] += red[threadIdx.x + s];
    __syncthreads();
  }
  float r = red[0];
  __syncthreads();
  return r;
}

__device__ void zero_buf(float *b, int n) {
  for (int i = blockIdx.x * NTHR + threadIdx.x; i < n; i += GSZ) b[i] = 0.f;
}

__device__ void sample_stats(const float *in, int len, float *red) {
  for (int n = blockIdx.x; n < 4; n += NBLK) {
    const float *p = in + n * len;
    float s = 0.f, ss = 0.f;
    for (int i = threadIdx.x; i < len; i += NTHR) {
      float v = p[i];
      s += v;
      ss += v * v;
    }
    s = block_reduce(s, red);
    ss = block_reduce(ss, red);
    if (threadIdx.x == 0) {
      float m = s / (float)len;
      float var = fmaxf(ss / (float)len - m * m, 0.f);
      g_m[n] = m;
      g_rs[n] = 1.f / (sqrtf(var) + 1e-8f);
    }
    __syncthreads();
  }
}

__device__ void standardize(const float *in, float *out, int len) {
  for (int i = blockIdx.x * NTHR + threadIdx.x; i < 4 * len; i += GSZ) {
    int n = i / len;
    out[i] = (in[i] - g_m[n]) * g_rs[n];
  }
}

__device__ void conv5x5(const float *__restrict__ in, const float *__restrict__ w,
                        const float *__restrict__ bias, float *__restrict__ out,
                        int Cin, int Cout, int HW, bool do_relu) {
  int npix = HW * HW;
  const int NJOB = 4 * Cout * npix;
  CHUNK_LOOP(NJOB) {
    int x = idx % HW;
    int t = idx / HW;
    int y = t % HW;
    t /= HW;
    int f = t % Cout;
    int n = t / Cout;
    float acc = bias ? bias[f] : 0.f;
    const float *wb = w + f * Cin * 25;
    for (int c = 0; c < Cin; ++c) {
      const float *ib = in + (n * Cin + c) * npix;
      const float *wc = wb + c * 25;
#pragma unroll
      for (int ky = 0; ky < 5; ++ky) {
        int yy = y + ky - 2;
        if ((unsigned)yy >= (unsigned)HW) continue;
#pragma unroll
        for (int kx = 0; kx < 5; ++kx) {
          int xx = x + kx - 2;
          if ((unsigned)xx >= (unsigned)HW) continue;
          acc += ib[yy * HW + xx] * wc[ky * 5 + kx];
        }
      }
    }
    out[idx] = do_relu ? fmaxf(acc, 0.f) : acc;
  }
}

__device__ void maxpool2(const float *__restrict__ in, float *__restrict__ out,
                         int C, int H) {
  int Ho = H / 2;
  int N = 4 * C * Ho * Ho;
  for (int idx = blockIdx.x * NTHR + threadIdx.x; idx < N; idx += GSZ) {
    int xo = idx % Ho;
    int t = idx / Ho;
    int yo = t % Ho;
    t /= Ho;
    const float *ib = in + t * H * H + (yo * 2) * H + xo * 2;
    out[idx] = fmaxf(fmaxf(ib[0], ib[1]), fmaxf(ib[H], ib[H + 1]));
  }
}

__device__ void bn_stats(const float *in, int C, int npix, float *red) {
  int cnt = 4 * npix;
  for (int c = blockIdx.x; c < C; c += NBLK) {
    float s = 0.f, ss = 0.f;
    for (int i = threadIdx.x; i < cnt; i += NTHR) {
      int n = i / npix, pp = i % npix;
      float v = in[(n * C + c) * npix + pp];
      s += v;
      ss += v * v;
    }
    s = block_reduce(s, red);
    ss = block_reduce(ss, red);
    if (threadIdx.x == 0) {
      float m = s / (float)cnt;
      float var = fmaxf(ss / (float)cnt - m * m, 0.f);
      g_m[c] = m;
      g_rs[c] = rsqrtf(var + 1e-5f);
    }
    __syncthreads();
  }
}

__device__ void bn_apply(float *buf, int C, int npix, const float *gam, const float *bet) {
  int N = 4 * C * npix;
  for (int i = blockIdx.x * NTHR + threadIdx.x; i < N; i += GSZ) {
    int c = (i / npix) % C;
    buf[i] = (buf[i] - g_m[c]) * g_rs[c] * gam[c] + bet[c];
  }
}

// ============ LCA2: F=32, C=16 ============
// phaseA: recon[n][c][36][36] = sum_{f,ky,kx} w[f,c,ky,kx] * a[n,f,Y-ky,X-kx]
// jobs (n, cgrp4, pix36x36) = 4*4*1296 = 20736
__device__ void lca2_phaseA(const float *__restrict__ a, float *__restrict__ recon,
                            const float *__restrict__ swA) {
  const int NJOB = 4 * 4 * 1296;
  CHUNK_LOOP(NJOB) {
    int pix = idx % 1296;
    int t = idx / 1296;
    int cg = t & 3, n = t >> 2;
    int Y = pix / 36, X = pix % 36;
    float a0 = 0.f, a1 = 0.f, a2 = 0.f, a3 = 0.f;
    const float *ab = a + n * 32768;
    const float *wb = swA + cg * 4;  // [f][tap][16c]
    for (int f = 0; f < 32; ++f) {
      const float *af = ab + f * 1024;
      const float *wf = wb + f * 400;
#pragma unroll
      for (int ky = 0; ky < 5; ++ky) {
        int y = Y - ky;
        if ((unsigned)y >= 32u) continue;
        const float *arow = af + y * 32;
#pragma unroll
        for (int kx = 0; kx < 5; ++kx) {
          int x = X - kx;
          if ((unsigned)x >= 32u) continue;
          float av = arow[x];
          float4 w = *(const float4 *)(wf + (ky * 5 + kx) * 16);
          a0 += av * w.x;
          a1 += av * w.y;
          a2 += av * w.z;
          a3 += av * w.w;
        }
      }
    }
    float *rb = recon + (n * 16 + cg * 4) * 1296 + pix;
    rb[0] = a0;
    rb[1296] = a1;
    rb[2592] = a2;
    rb[3888] = a3;
  }
}

// phaseB: inhib[f] = sum_{c,tap} w[f,c,tap]*recon[c][y+ky][x+kx]; u update; a out.
// jobs (n, fgrp4 of 8, pix32x32) = 4*8*1024 = 32768
__device__ void lca2_phaseB(float *__restrict__ u, float *__restrict__ anew,
                            const float *__restrict__ recon,
                            const float *__restrict__ drive,
                            const float *__restrict__ swB) {
  const int NJOB = 4 * 8 * 1024;
  CHUNK_LOOP(NJOB) {
    int pix = idx & 1023;
    int t = idx >> 10;
    int g = t & 7, n = t >> 3;
    int y = pix >> 5, x = pix & 31;
    float acc0 = 0.f, acc1 = 0.f, acc2 = 0.f, acc3 = 0.f;
    const float *rb = recon + n * 16 * 1296;
    const float *wb = swB + g * 4;  // [c][tap][32f]
    for (int c = 0; c < 16; ++c) {
      const float *rc = rb + c * 1296;
      const float *wc = wb + c * 800;
#pragma unroll
      for (int ky = 0; ky < 5; ++ky) {
        const float *rrow = rc + (y + ky) * 36 + x;
#pragma unroll
        for (int kx = 0; kx < 5; ++kx) {
          float rv = rrow[kx];
          float4 w = *(const float4 *)(wc + (ky * 5 + kx) * 32);
          acc0 += rv * w.x;
          acc1 += rv * w.y;
          acc2 += rv * w.z;
          acc3 += rv * w.w;
        }
      }
    }
    float inh[4] = {acc0, acc1, acc2, acc3};
#pragma unroll
    for (int j = 0; j < 4; ++j) {
      int i = (n * 32 + g * 4 + j) * 1024 + pix;
      float uv = u[i];
      float av = fmaxf(uv - 0.5f, 0.f);
      float un = uv + 0.001f * (drive[i] - uv - inh[j] + av);
      u[i] = un;
      anew[i] = fmaxf(un - 0.5f, 0.f);
    }
  }
}

// ============ LCA1: F=16, C=3 (padded to 4) ============
// phaseA with 2 f-partials: jobs (part2, n, pix) = 2*4*1296 = 10368
__device__ void lca1_phaseA(const float *__restrict__ a, float *__restrict__ recon,
                            const float *__restrict__ swA) {
  const int NJOB = 2 * 4 * 1296;
  CHUNK_LOOP(NJOB) {
    int pix = idx % 1296;
    int t = idx / 1296;
    int n = t & 3, part = t >> 2;
    int Y = pix / 36, X = pix % 36;
    float a0 = 0.f, a1 = 0.f, a2 = 0.f;
    const float *ab = a + n * 16384;
    for (int ff = 0; ff < 8; ++ff) {
      int f = part * 8 + ff;
      const float *af = ab + f * 1024;
      const float *wf = swA + f * 100;  // [f][tap][4c padded]
#pragma unroll
      for (int ky = 0; ky < 5; ++ky) {
        int y = Y - ky;
        if ((unsigned)y >= 32u) continue;
        const float *arow = af + y * 32;
#pragma unroll
        for (int kx = 0; kx < 5; ++kx) {
          int x = X - kx;
          if ((unsigned)x >= 32u) continue;
          float av = arow[x];
          float4 w = *(const float4 *)(wf + (ky * 5 + kx) * 4);
          a0 += av * w.x;
          a1 += av * w.y;
          a2 += av * w.z;
        }
      }
    }
    float *rb = recon + ((part * 4 + n) * 3) * 1296 + pix;
    rb[0] = a0;
    rb[1296] = a1;
    rb[2592] = a2;
  }
}

// jobs (n, fgrp4 of 4, pix) = 4*4*1024 = 16384
__device__ void lca1_phaseB(float *__restrict__ u, float *__restrict__ anew,
                            const float *__restrict__ recon,
                            const float *__restrict__ drive,
                            const float *__restrict__ swB) {
  const int NJOB = 4 * 4 * 1024;
  CHUNK_LOOP(NJOB) {
    int pix = idx & 1023;
    int t = idx >> 10;
    int g = t & 3, n = t >> 2;
    int y = pix >> 5, x = pix & 31;
    float acc0 = 0.f, acc1 = 0.f, acc2 = 0.f, acc3 = 0.f;
    const float *rb0 = recon + (n * 3) * 1296;
    const float *rb1 = rb0 + 12 * 1296;
    const float *wb = swB + g * 4;  // [c][tap][16f]
    for (int c = 0; c < 3; ++c) {
      const float *rc0 = rb0 + c * 1296;
      const float *rc1 = rb1 + c * 1296;
      const float *wc = wb + c * 400;
#pragma unroll
      for (int ky = 0; ky < 5; ++ky) {
        int off = (y + ky) * 36 + x;
#pragma unroll
        for (int kx = 0; kx < 5; ++kx) {
          float rv = rc0[off + kx] + rc1[off + kx];
          float4 w = *(const float4 *)(wc + (ky * 5 + kx) * 16);
          acc0 += rv * w.x;
          acc1 += rv * w.y;
          acc2 += rv * w.z;
          acc3 += rv * w.w;
        }
      }
    }
    float inh[4] = {acc0, acc1, acc2, acc3};
#pragma unroll
    for (int j = 0; j < 4; ++j) {
      int i = (n * 16 + g * 4 + j) * 1024 + pix;
      float uv = u[i];
      float av = fmaxf(uv - 0.5f, 0.f);
      float un = uv + 0.001f * (drive[i] - uv - inh[j] + av);
      u[i] = un;
      anew[i] = fmaxf(un - 0.5f, 0.f);
    }
  }
}

__device__ void fc(const float *__restrict__ in, const float *__restrict__ w,
                   const float *__restrict__ bias, float *__restrict__ out,
                   int K, int J, bool do_relu) {
  int N = 4 * J;
  for (int idx = blockIdx.x * NTHR + threadIdx.x; idx < N; idx += GSZ) {
    int j = idx % J, n = idx / J;
    float acc = bias[j];
    const float *wr = w + j * K;
    const float *ir = in + n * K;
    for (int k = 0; k < K; ++k) acc += ir[k] * wr[k];
    out[idx] = do_relu ? fmaxf(acc, 0.f) : acc;
  }
}

// ===================== the whole network, one persistent kernel =====================
__global__ void __launch_bounds__(NTHR, 1) splitnn_kernel(P p) {
  extern __shared__ float smem[];
  float *swA = smem + SW_A;
  float *swB = smem + SW_B;
  float *red = smem + RED_OFF;

  // ---- stage LCA1 weights: swA1 [f][tap][4c], swB1 [c][tap][16f] ----
  for (int i = threadIdx.x; i < 1600; i += NTHR) {
    int f = i / 100, r = i % 100, tap = r >> 2, c = r & 3;
    swA[i] = (c < 3) ? p.w1[(f * 3 + c) * 25 + tap] : 0.f;
  }
  for (int i = threadIdx.x; i < 1200; i += NTHR) {
    int c = i / 400, r = i % 400, tap = r >> 4, f = r & 15;
    swB[i] = p.w1[(f * 3 + c) * 25 + tap];
  }

  // ---- standardize input, drive1, u=a=0 ----
  sample_stats(p.x, 3072, red);
  grid_sync();
  standardize(p.x, g_xs, 3072);
  zero_buf(g_u, 65536);
  zero_buf(g_a, 65536);
  grid_sync();
  conv5x5(g_xs, p.w1, nullptr, g_drive, 3, 16, 32, false);
  grid_sync();

  // ---- LCA1 ----
  for (int it = 0; it < 500; ++it) {
    lca1_phaseA(g_a, g_recon, swA);
    grid_sync();
    lca1_phaseB(g_u, g_a, g_recon, g_drive, swB);
    grid_sync();
  }
  // g_a holds the final sparse code
  bn_stats(g_a, 16, 1024, red);
  grid_sync();
  bn_apply(g_a, 16, 1024, p.bn1g, p.bn1b);
  grid_sync();

  // ---- stage LCA2 weights, standardize, drive2 ----
  sample_stats(g_a, 16384, red);
  grid_sync();
  standardize(g_a, g_xs, 16384);
  grid_sync();
  conv5x5(g_xs, p.w2, nullptr, g_drive, 16, 32, 32, false);
  zero_buf(g_u, 131072);
  for (int i = threadIdx.x; i < 12800; i += NTHR) {
    int f = i / 400, r = i % 400, tap = r >> 4, c = r & 15;
    swA[i] = p.w2[(f * 16 + c) * 25 + tap];
  }
  for (int i = threadIdx.x; i < 12800; i += NTHR) {
    int c = i / 800, r = i % 800, tap = r >> 5, f = r & 31;
    swB[i] = p.w2[(f * 16 + c) * 25 + tap];
  }
  grid_sync();
  zero_buf(g_a, 131072);
  grid_sync();

  // ---- LCA2 ----
  for (int it = 0; it < 500; ++it) {
    lca2_phaseA(g_a, g_recon, swA);
    grid_sync();
    lca2_phaseB(g_u, g_a, g_recon, g_drive, swB);
    grid_sync();
  }
  maxpool2(g_a, g_xs, 32, 32);  // -> [4,32,16,16]
  grid_sync();
  bn_stats(g_xs, 32, 256, red);
  grid_sync();
  bn_apply(g_xs, 32, 256, p.bn2g, p.bn2b);
  grid_sync();

  // ---- conv tail ----
  conv5x5(g_xs, p.wc1, p.bc1, g_h, 32, 64, 16, true);
  grid_sync();
  maxpool2(g_h, g_drive, 64, 16);
  grid_sync();
  bn_stats(g_drive, 64, 64, red);
  grid_sync();
  bn_apply(g_drive, 64, 64, p.bn3g, p.bn3b);
  grid_sync();
  conv5x5(g_drive, p.wc2, p.bc2, g_h, 64, 128, 8, true);
  grid_sync();
  maxpool2(g_h, g_xs, 128, 8);
  grid_sync();
  bn_stats(g_xs, 128, 16, red);
  grid_sync();
  bn_apply(g_xs, 128, 16, p.bn4g, p.bn4b);
  grid_sync();
  conv5x5(g_xs, p.wc3, p.bc3, g_h, 128, 256, 4, true);
  grid_sync();
  maxpool2(g_h, g_drive, 256, 4);  // [4,256,2,2] == flat [4,1024]
  grid_sync();
  bn_stats(g_drive, 256, 4, red);
  grid_sync();
  bn_apply(g_drive, 256, 4, p.bn5g, p.bn5b);
  grid_sync();

  // ---- classifier ----
  fc(g_drive, p.wf1, p.bf1, g_fc, 1024, 512, true);
  grid_sync();
  fc(g_fc, p.wf2, p.bf2, p.out, 512, 10, false);
}

extern "C" void kernel_launch(void *const *d_in, const int *in_sizes, int n_in,
                              void *d_out, int out_size) {
  (void)in_sizes;
  (void)n_in;
  (void)out_size;
  P p;
  p.x = (const float *)d_in[0];
  p.w1 = (const float *)d_in[1];
  p.w2 = (const float *)d_in[2];
  p.bn1g = (const float *)d_in[3];
  p.bn1b = (const float *)d_in[4];
  p.bn2g = (const float *)d_in[5];
  p.bn2b = (const float *)d_in[6];
  p.wc1 = (const float *)d_in[7];
  p.bc1 = (const float *)d_in[8];
  p.bn3g = (const float *)d_in[9];
  p.bn3b = (const float *)d_in[10];
  p.wc2 = (const float *)d_in[11];
  p.bc2 = (const float *)d_in[12];
  p.bn4g = (const float *)d_in[13];
  p.bn4b = (const float *)d_in[14];
  p.wc3 = (const float *)d_in[15];
  p.bc3 = (const float *)d_in[16];
  p.bn5g = (const float *)d_in[17];
  p.bn5b = (const float *)d_in[18];
  p.wf1 = (const float *)d_in[19];
  p.bf1 = (const float *)d_in[20];
  p.wf2 = (const float *)d_in[21];
  p.bf2 = (const float *)d_in[22];
  p.out = (float *)d_out;

  cudaFuncSetAttribute(reinterpret_cast<const void *>(splitnn_kernel),
                       cudaFuncAttributeMaxDynamicSharedMemorySize, SMEM_BYTES);
  splitnn_kernel<<<NBLK, NTHR, SMEM_BYTES>>>(p);
}

// round 4
// speedup vs baseline: 1.7277x; 1.3481x over previous
#include <cuda_runtime.h>

#define NBLK 148
#define NTHR 512
#define GSZ (NBLK * NTHR)

// smem layout (floats)
#define SW_A 0         // 12800: phaseA weights [f][tap][c]
#define SW_B 12800     // 12800: phaseB weights [c][tap][f]
#define RED_OFF 25600  // 512: reduction scratch
#define SMEM_FLOATS 26112
#define SMEM_BYTES (SMEM_FLOATS * 4)

struct P {
  const float *x, *w1, *w2;
  const float *bn1g, *bn1b, *bn2g, *bn2b;
  const float *wc1, *bc1, *bn3g, *bn3b;
  const float *wc2, *bc2, *bn4g, *bn4b;
  const float *wc3, *bc3, *bn5g, *bn5b;
  const float *wf1, *bf1, *wf2, *bf2;
  float *out;
};

// ---- persistent-kernel scratch (device globals; no allocation) ----
__device__ unsigned int g_cnt = 0;
__device__ volatile unsigned int g_gen = 0;

__device__ float g_xs[131072];
__device__ float g_drive[131072];
__device__ float g_u[131072];
__device__ float g_a[131072];
__device__ float g_recon[165888];  // LCA2: [n][16c][1296][2p]; LCA1: [n][3c][1296][4p]
__device__ float g_h[131072];
__device__ float g_m[256];
__device__ float g_rs[256];
__device__ float g_fc[2048];
__device__ float g_fcp[16384];

// each block gets a contiguous chunk of jobs
#define CHUNK_LOOP(NJOB)                                                   \
  const int _ck = ((NJOB) + NBLK - 1) / NBLK;                              \
  const int _j0 = blockIdx.x * _ck;                                        \
  const int _j1 = (_j0 + _ck < (NJOB)) ? (_j0 + _ck) : (NJOB);             \
  for (int idx = _j0 + (int)threadIdx.x; idx < _j1; idx += NTHR)

// ---- software grid barrier (148 blocks, 1/SM, co-resident) ----
__device__ __forceinline__ void grid_sync() {
  __syncthreads();
  if (threadIdx.x == 0) {
    unsigned int gen = g_gen;
    __threadfence();  // release
    if (atomicAdd(&g_cnt, 1u) == (unsigned)(NBLK - 1)) {
      g_cnt = 0u;
      __threadfence();
      g_gen = gen + 1u;
    } else {
      while (g_gen == gen) {}
      __threadfence();  // acquire (CCTL.IVALL -> drop stale L1)
    }
  }
  __syncthreads();
}

__device__ __forceinline__ float block_reduce(float v, float *red) {
  red[threadIdx.x] = v;
  __syncthreads();
#pragma unroll
  for (int s = NTHR / 2; s > 0; s >>= 1) {
    if (threadIdx.x < s) red[threadIdx.x] += red[threadIdx.x + s];
    __syncthreads();
  }
  float r = red[0];
  __syncthreads();
  return r;
}

__device__ void zero_buf(float *b, int n) {
  for (int i = blockIdx.x * NTHR + threadIdx.x; i < n; i += GSZ) b[i] = 0.f;
}

__device__ void sample_stats(const float *in, int len, float *red) {
  for (int n = blockIdx.x; n < 4; n += NBLK) {
    const float *p = in + n * len;
    float s = 0.f, ss = 0.f;
    for (int i = threadIdx.x; i < len; i += NTHR) {
      float v = p[i];
      s += v;
      ss += v * v;
    }
    s = block_reduce(s, red);
    ss = block_reduce(ss, red);
    if (threadIdx.x == 0) {
      float m = s / (float)len;
      float var = fmaxf(ss / (float)len - m * m, 0.f);
      g_m[n] = m;
      g_rs[n] = 1.f / (sqrtf(var) + 1e-8f);
    }
    __syncthreads();
  }
}

__device__ void standardize(const float *in, float *out, int len) {
  for (int i = blockIdx.x * NTHR + threadIdx.x; i < 4 * len; i += GSZ) {
    int n = i / len;
    out[i] = (in[i] - g_m[n]) * g_rs[n];
  }
}

__device__ void conv5x5(const float *__restrict__ in, const float *__restrict__ w,
                        const float *__restrict__ bias, float *__restrict__ out,
                        int Cin, int Cout, int HW, bool do_relu) {
  int npix = HW * HW;
  const int NJOB = 4 * Cout * npix;
  CHUNK_LOOP(NJOB) {
    int x = idx % HW;
    int t = idx / HW;
    int y = t % HW;
    t /= HW;
    int f = t % Cout;
    int n = t / Cout;
    float acc = bias ? bias[f] : 0.f;
    const float *wb = w + f * Cin * 25;
    for (int c = 0; c < Cin; ++c) {
      const float *ib = in + (n * Cin + c) * npix;
      const float *wc = wb + c * 25;
#pragma unroll
      for (int ky = 0; ky < 5; ++ky) {
        int yy = y + ky - 2;
        if ((unsigned)yy >= (unsigned)HW) continue;
#pragma unroll
        for (int kx = 0; kx < 5; ++kx) {
          int xx = x + kx - 2;
          if ((unsigned)xx >= (unsigned)HW) continue;
          acc += ib[yy * HW + xx] * wc[ky * 5 + kx];
        }
      }
    }
    out[idx] = do_relu ? fmaxf(acc, 0.f) : acc;
  }
}

__device__ void maxpool2(const float *__restrict__ in, float *__restrict__ out,
                         int C, int H) {
  int Ho = H / 2;
  int N = 4 * C * Ho * Ho;
  for (int idx = blockIdx.x * NTHR + threadIdx.x; idx < N; idx += GSZ) {
    int xo = idx % Ho;
    int t = idx / Ho;
    int yo = t % Ho;
    t /= Ho;
    const float *ib = in + t * H * H + (yo * 2) * H + xo * 2;
    out[idx] = fmaxf(fmaxf(ib[0], ib[1]), fmaxf(ib[H], ib[H + 1]));
  }
}

__device__ void bn_stats(const float *in, int C, int npix, float *red) {
  int cnt = 4 * npix;
  for (int c = blockIdx.x; c < C; c += NBLK) {
    float s = 0.f, ss = 0.f;
    for (int i = threadIdx.x; i < cnt; i += NTHR) {
      int n = i / npix, pp = i % npix;
      float v = in[(n * C + c) * npix + pp];
      s += v;
      ss += v * v;
    }
    s = block_reduce(s, red);
    ss = block_reduce(ss, red);
    if (threadIdx.x == 0) {
      float m = s / (float)cnt;
      float var = fmaxf(ss / (float)cnt - m * m, 0.f);
      g_m[c] = m;
      g_rs[c] = rsqrtf(var + 1e-5f);
    }
    __syncthreads();
  }
}

__device__ void bn_apply(float *buf, int C, int npix, const float *gam, const float *bet) {
  int N = 4 * C * npix;
  for (int i = blockIdx.x * NTHR + threadIdx.x; i < N; i += GSZ) {
    int c = (i / npix) % C;
    buf[i] = (buf[i] - g_m[c]) * g_rs[c] * gam[c] + bet[c];
  }
}

// ============ LCA2: F=32, C=16 ============
// phaseA: 2 f-partials. recon[n][c][1296][2] (partials interleaved).
// jobs (part, n, cg4, pixE) = 2*4*4*1296 = 41472
__device__ void lca2_phaseA(const float *__restrict__ a, float *__restrict__ recon,
                            const float *__restrict__ swA) {
  const int NJOB = 2 * 4 * 4 * 1296;
  CHUNK_LOOP(NJOB) {
    int pix = idx % 1296;
    int t = idx / 1296;
    int cg = t & 3;
    t >>= 2;
    int n = t & 3;
    int part = t >> 2;
    int Y = pix / 36, X = pix % 36;
    float a0 = 0.f, a1 = 0.f, a2 = 0.f, a3 = 0.f;
    const float *ab = a + n * 32768 + part * 16384;
    const float *wb = swA + part * 6400 + cg * 4;  // [f][tap][16c]
    for (int ff = 0; ff < 16; ++ff) {
      const float *af = ab + ff * 1024;
      const float *wf = wb + ff * 400;
#pragma unroll
      for (int ky = 0; ky < 5; ++ky) {
        int y = Y - ky;
        if ((unsigned)y >= 32u) continue;
        const float *arow = af + y * 32;
#pragma unroll
        for (int kx = 0; kx < 5; ++kx) {
          int x = X - kx;
          if ((unsigned)x >= 32u) continue;
          float av = arow[x];
          float4 w = *(const float4 *)(wf + (ky * 5 + kx) * 16);
          a0 += av * w.x;
          a1 += av * w.y;
          a2 += av * w.z;
          a3 += av * w.w;
        }
      }
    }
    float *rb = recon + ((n * 16 + cg * 4) * 1296 + pix) * 2 + part;
    rb[0] = a0;
    rb[2592] = a1;
    rb[5184] = a2;
    rb[7776] = a3;
  }
}

// phaseB: fg=2. jobs (n, g16, pix) = 4*16*1024 = 65536
__device__ void lca2_phaseB(float *__restrict__ u, float *__restrict__ anew,
                            const float *__restrict__ recon,
                            const float *__restrict__ drive,
                            const float *__restrict__ swB) {
  const int NJOB = 4 * 16 * 1024;
  CHUNK_LOOP(NJOB) {
    int pix = idx & 1023;
    int t = idx >> 10;
    int g = t & 15, n = t >> 4;
    int y = pix >> 5, x = pix & 31;
    float acc0 = 0.f, acc1 = 0.f;
    const float *rb = recon + n * 16 * 2592;  // [c][1296][2]
    const float *wb = swB + g * 2;            // [c][tap][32f]
    for (int c = 0; c < 16; ++c) {
      const float *rc = rb + c * 2592;
      const float *wc = wb + c * 800;
#pragma unroll
      for (int ky = 0; ky < 5; ++ky) {
        const float2 *rrow = (const float2 *)(rc + ((y + ky) * 36 + x) * 2);
#pragma unroll
        for (int kx = 0; kx < 5; ++kx) {
          float2 r2 = rrow[kx];
          float rv = r2.x + r2.y;
          float2 w = *(const float2 *)(wc + (ky * 5 + kx) * 32);
          acc0 += rv * w.x;
          acc1 += rv * w.y;
        }
      }
    }
    float inh[2] = {acc0, acc1};
#pragma unroll
    for (int j = 0; j < 2; ++j) {
      int i = (n * 32 + g * 2 + j) * 1024 + pix;
      float uv = u[i];
      float av = fmaxf(uv - 0.5f, 0.f);
      float un = uv + 0.001f * (drive[i] - uv - inh[j] + av);
      u[i] = un;
      anew[i] = fmaxf(un - 0.5f, 0.f);
    }
  }
}

// ============ LCA1: F=16, C=3 (pad 4) ============
// phaseA: 4 f-partials. recon[n][c][1296][4]. jobs = 4*4*1296 = 20736
__device__ void lca1_phaseA(const float *__restrict__ a, float *__restrict__ recon,
                            const float *__restrict__ swA) {
  const int NJOB = 4 * 4 * 1296;
  CHUNK_LOOP(NJOB) {
    int pix = idx % 1296;
    int t = idx / 1296;
    int n = t & 3, part = t >> 2;
    int Y = pix / 36, X = pix % 36;
    float a0 = 0.f, a1 = 0.f, a2 = 0.f;
    const float *ab = a + n * 16384 + part * 4096;
    const float *wb = swA + part * 400;  // [f][tap][4c]
    for (int ff = 0; ff < 4; ++ff) {
      const float *af = ab + ff * 1024;
      const float *wf = wb + ff * 100;
#pragma unroll
      for (int ky = 0; ky < 5; ++ky) {
        int y = Y - ky;
        if ((unsigned)y >= 32u) continue;
        const float *arow = af + y * 32;
#pragma unroll
        for (int kx = 0; kx < 5; ++kx) {
          int x = X - kx;
          if ((unsigned)x >= 32u) continue;
          float av = arow[x];
          float4 w = *(const float4 *)(wf + (ky * 5 + kx) * 4);
          a0 += av * w.x;
          a1 += av * w.y;
          a2 += av * w.z;
        }
      }
    }
    float *rb = recon + ((n * 3) * 1296 + pix) * 4 + part;
    rb[0] = a0;
    rb[5184] = a1;
    rb[10368] = a2;
  }
}

// phaseB: fg=2. jobs (n, g8, pix) = 4*8*1024 = 32768
__device__ void lca1_phaseB(float *__restrict__ u, float *__restrict__ anew,
                            const float *__restrict__ recon,
                            const float *__restrict__ drive,
                            const float *__restrict__ swB) {
  const int NJOB = 4 * 8 * 1024;
  CHUNK_LOOP(NJOB) {
    int pix = idx & 1023;
    int t = idx >> 10;
    int g = t & 7, n = t >> 3;
    int y = pix >> 5, x = pix & 31;
    float acc0 = 0.f, acc1 = 0.f;
    const float *rb = recon + n * 3 * 5184;  // [c][1296][4]
    const float *wb = swB + g * 2;           // [c][tap][16f]
    for (int c = 0; c < 3; ++c) {
      const float *rc = rb + c * 5184;
      const float *wc = wb + c * 400;
#pragma unroll
      for (int ky = 0; ky < 5; ++ky) {
        const float4 *rrow = (const float4 *)(rc + ((y + ky) * 36 + x) * 4);
#pragma unroll
        for (int kx = 0; kx < 5; ++kx) {
          float4 r4 = rrow[kx];
          float rv = (r4.x + r4.y) + (r4.z + r4.w);
          float2 w = *(const float2 *)(wc + (ky * 5 + kx) * 16);
          acc0 += rv * w.x;
          acc1 += rv * w.y;
        }
      }
    }
    float inh[2] = {acc0, acc1};
#pragma unroll
    for (int j = 0; j < 2; ++j) {
      int i = (n * 16 + g * 2 + j) * 1024 + pix;
      float uv = u[i];
      float av = fmaxf(uv - 0.5f, 0.f);
      float un = uv + 0.001f * (drive[i] - uv - inh[j] + av);
      u[i] = un;
      anew[i] = fmaxf(un - 0.5f, 0.f);
    }
  }
}

// ---- split-K fully-connected ----
__device__ void fc_partial(const float *__restrict__ in, const float *__restrict__ w,
                           float *__restrict__ part, int K, int J, int KP) {
  int kw = K / KP;
  const int NJOB = 4 * J * KP;
  CHUNK_LOOP(NJOB) {
    int kp = idx % KP;
    int t = idx / KP;
    int j = t % J, n = t / J;
    const float *ir = in + n * K + kp * kw;
    const float *wr = w + j * K + kp * kw;
    float acc = 0.f;
    for (int k = 0; k < kw; ++k) acc += ir[k] * wr[k];
    part[idx] = acc;
  }
}

__device__ void fc_reduce(const float *__restrict__ part, const float *__restrict__ bias,
                          float *__restrict__ out, int J, int KP, bool do_relu) {
  const int NJOB = 4 * J;
  for (int idx = blockIdx.x * NTHR + threadIdx.x; idx < NJOB; idx += GSZ) {
    float acc = bias[idx % J];
    for (int kp = 0; kp < KP; ++kp) acc += part[idx * KP + kp];
    out[idx] = do_relu ? fmaxf(acc, 0.f) : acc;
  }
}

// ===================== the whole network, one persistent kernel =====================
__global__ void __launch_bounds__(NTHR, 1) splitnn_kernel(P p) {
  extern __shared__ float smem[];
  float *swA = smem + SW_A;
  float *swB = smem + SW_B;
  float *red = smem + RED_OFF;

  // ---- stage LCA1 weights: swA1 [f][tap][4c], swB1 [c][tap][16f] ----
  for (int i = threadIdx.x; i < 1600; i += NTHR) {
    int f = i / 100, r = i % 100, tap = r >> 2, c = r & 3;
    swA[i] = (c < 3) ? p.w1[(f * 3 + c) * 25 + tap] : 0.f;
  }
  for (int i = threadIdx.x; i < 1200; i += NTHR) {
    int c = i / 400, r = i % 400, tap = r >> 4, f = r & 15;
    swB[i] = p.w1[(f * 3 + c) * 25 + tap];
  }

  // ---- standardize input, drive1, u=a=0 ----
  sample_stats(p.x, 3072, red);
  grid_sync();
  standardize(p.x, g_xs, 3072);
  zero_buf(g_u, 65536);
  zero_buf(g_a, 65536);
  grid_sync();
  conv5x5(g_xs, p.w1, nullptr, g_drive, 3, 16, 32, false);
  grid_sync();

  // ---- LCA1 ----
  for (int it = 0; it < 500; ++it) {
    lca1_phaseA(g_a, g_recon, swA);
    grid_sync();
    lca1_phaseB(g_u, g_a, g_recon, g_drive, swB);
    grid_sync();
  }
  bn_stats(g_a, 16, 1024, red);
  grid_sync();
  bn_apply(g_a, 16, 1024, p.bn1g, p.bn1b);
  grid_sync();

  // ---- stage LCA2 weights, standardize, drive2 ----
  sample_stats(g_a, 16384, red);
  grid_sync();
  standardize(g_a, g_xs, 16384);
  grid_sync();
  conv5x5(g_xs, p.w2, nullptr, g_drive, 16, 32, 32, false);
  zero_buf(g_u, 131072);
  for (int i = threadIdx.x; i < 12800; i += NTHR) {
    int f = i / 400, r = i % 400, tap = r >> 4, c = r & 15;
    swA[i] = p.w2[(f * 16 + c) * 25 + tap];
  }
  for (int i = threadIdx.x; i < 12800; i += NTHR) {
    int c = i / 800, r = i % 800, tap = r >> 5, f = r & 31;
    swB[i] = p.w2[(f * 16 + c) * 25 + tap];
  }
  grid_sync();
  zero_buf(g_a, 131072);
  grid_sync();

  // ---- LCA2 ----
  for (int it = 0; it < 500; ++it) {
    lca2_phaseA(g_a, g_recon, swA);
    grid_sync();
    lca2_phaseB(g_u, g_a, g_recon, g_drive, swB);
    grid_sync();
  }
  maxpool2(g_a, g_xs, 32, 32);
  grid_sync();
  bn_stats(g_xs, 32, 256, red);
  grid_sync();
  bn_apply(g_xs, 32, 256, p.bn2g, p.bn2b);
  grid_sync();

  // ---- conv tail ----
  conv5x5(g_xs, p.wc1, p.bc1, g_h, 32, 64, 16, true);
  grid_sync();
  maxpool2(g_h, g_drive, 64, 16);
  grid_sync();
  bn_stats(g_drive, 64, 64, red);
  grid_sync();
  bn_apply(g_drive, 64, 64, p.bn3g, p.bn3b);
  grid_sync();
  conv5x5(g_drive, p.wc2, p.bc2, g_h, 64, 128, 8, true);
  grid_sync();
  maxpool2(g_h, g_xs, 128, 8);
  grid_sync();
  bn_stats(g_xs, 128, 16, red);
  grid_sync();
  bn_apply(g_xs, 128, 16, p.bn4g, p.bn4b);
  grid_sync();
  conv5x5(g_xs, p.wc3, p.bc3, g_h, 128, 256, 4, true);
  grid_sync();
  maxpool2(g_h, g_drive, 256, 4);  // [4,256,2,2] == flat [4,1024]
  grid_sync();
  bn_stats(g_drive, 256, 4, red);
  grid_sync();
  bn_apply(g_drive, 256, 4, p.bn5g, p.bn5b);
  grid_sync();

  // ---- classifier (split-K) ----
  fc_partial(g_drive, p.wf1, g_fcp, 1024, 512, 8);
  grid_sync();
  fc_reduce(g_fcp, p.bf1, g_fc, 512, 8, true);
  grid_sync();
  fc_partial(g_fc, p.wf2, g_fcp, 512, 10, 8);
  grid_sync();
  fc_reduce(g_fcp, p.bf2, p.out, 10, 8, false);
}

extern "C" void kernel_launch(void *const *d_in, const int *in_sizes, int n_in,
                              void *d_out, int out_size) {
  (void)in_sizes;
  (void)n_in;
  (void)out_size;
  P p;
  p.x = (const float *)d_in[0];
  p.w1 = (const float *)d_in[1];
  p.w2 = (const float *)d_in[2];
  p.bn1g = (const float *)d_in[3];
  p.bn1b = (const float *)d_in[4];
  p.bn2g = (const float *)d_in[5];
  p.bn2b = (const float *)d_in[6];
  p.wc1 = (const float *)d_in[7];
  p.bc1 = (const float *)d_in[8];
  p.bn3g = (const float *)d_in[9];
  p.bn3b = (const float *)d_in[10];
  p.wc2 = (const float *)d_in[11];
  p.bc2 = (const float *)d_in[12];
  p.bn4g = (const float *)d_in[13];
  p.bn4b = (const float *)d_in[14];
  p.wc3 = (const float *)d_in[15];
  p.bc3 = (const float *)d_in[16];
  p.bn5g = (const float *)d_in[17];
  p.bn5b = (const float *)d_in[18];
  p.wf1 = (const float *)d_in[19];
  p.bf1 = (const float *)d_in[20];
  p.wf2 = (const float *)d_in[21];
  p.bf2 = (const float *)d_in[22];
  p.out = (float *)d_out;

  cudaFuncSetAttribute(reinterpret_cast<const void *>(splitnn_kernel),
                       cudaFuncAttributeMaxDynamicSharedMemorySize, SMEM_BYTES);
  splitnn_kernel<<<NBLK, NTHR, SMEM_BYTES>>>(p);
}

// round 5
// speedup vs baseline: 3.0024x; 1.7379x over previous
#include <cuda_runtime.h>

#define NBLK 148
#define NTHR 512
#define GSZ (NBLK * NTHR)

typedef unsigned long long ull;

// smem layout (floats)
#define SW_A 0         // 12800: phaseA weights
#define SW_B 12800     // 12800: phaseB weights
#define RED_OFF 25600  // 512: reduction scratch
#define SMEM_FLOATS 26112
#define SMEM_BYTES (SMEM_FLOATS * 4)

struct P {
  const float *x, *w1, *w2;
  const float *bn1g, *bn1b, *bn2g, *bn2b;
  const float *wc1, *bc1, *bn3g, *bn3b;
  const float *wc2, *bc2, *bn4g, *bn4b;
  const float *wc3, *bc3, *bn5g, *bn5b;
  const float *wf1, *bf1, *wf2, *bf2;
  float *out;
};

// ---- f32x2 packed helpers (sm_103a FFMA2 path) ----
__device__ __forceinline__ ull dup2(float v) {
  ull r;
  asm("mov.b64 %0, {%1, %1};" : "=l"(r) : "f"(v));
  return r;
}
__device__ __forceinline__ void unpack2(ull p, float &lo, float &hi) {
  asm("mov.b64 {%0, %1}, %2;" : "=f"(lo), "=f"(hi) : "l"(p));
}
__device__ __forceinline__ ull ffma2(ull a, ull b, ull c) {
  ull d;
  asm("fma.rn.f32x2 %0, %1, %2, %3;" : "=l"(d) : "l"(a), "l"(b), "l"(c));
  return d;
}
__device__ __forceinline__ ull add2(ull a, ull b) {
  ull d;
  asm("add.rn.f32x2 %0, %1, %2;" : "=l"(d) : "l"(a), "l"(b));
  return d;
}

// ---- persistent-kernel scratch (device globals; no allocation) ----
__device__ unsigned int g_cnt = 0;
__device__ volatile unsigned int g_gen = 0;

__device__ float g_xs[131072];
__device__ float g_drive[131072];
__device__ float g_u[131072];
__device__ float g_a[204800];      // PADDED code a: [n][F][40][40], zero border
__device__ float g_recon[165888];  // LCA2: [n][16c][1296][2p]; LCA1: [n][3c][1296][4p]
__device__ float g_h[131072];
__device__ float g_m[256];
__device__ float g_rs[256];
__device__ float g_fc[2048];
__device__ float g_fcp[16384];

// each block gets a contiguous chunk of jobs
#define CHUNK_LOOP(NJOB)                                                   \
  const int _ck = ((NJOB) + NBLK - 1) / NBLK;                              \
  const int _j0 = blockIdx.x * _ck;                                        \
  const int _j1 = (_j0 + _ck < (NJOB)) ? (_j0 + _ck) : (NJOB);             \
  for (int idx = _j0 + (int)threadIdx.x; idx < _j1; idx += NTHR)

// ---- software grid barrier (148 blocks, 1/SM, co-resident) ----
__device__ __forceinline__ void grid_sync() {
  __syncthreads();
  if (threadIdx.x == 0) {
    unsigned int gen = g_gen;
    __threadfence();  // release
    if (atomicAdd(&g_cnt, 1u) == (unsigned)(NBLK - 1)) {
      g_cnt = 0u;
      __threadfence();
      g_gen = gen + 1u;
    } else {
      while (g_gen == gen) {}
      __threadfence();  // acquire (CCTL.IVALL -> drop stale L1)
    }
  }
  __syncthreads();
}

__device__ __forceinline__ float block_reduce(float v, float *red) {
  red[threadIdx.x] = v;
  __syncthreads();
#pragma unroll
  for (int s = NTHR / 2; s > 0; s >>= 1) {
    if (threadIdx.x < s) red[threadIdx.x] += red[threadIdx.x + s];
    __syncthreads();
  }
  float r = red[0];
  __syncthreads();
  return r;
}

__device__ void zero_buf(float *b, int n) {
  for (int i = blockIdx.x * NTHR + threadIdx.x; i < n; i += GSZ) b[i] = 0.f;
}

__device__ void sample_stats(const float *in, int len, float *red) {
  for (int n = blockIdx.x; n < 4; n += NBLK) {
    const float *p = in + n * len;
    float s = 0.f, ss = 0.f;
    for (int i = threadIdx.x; i < len; i += NTHR) {
      float v = p[i];
      s += v;
      ss += v * v;
    }
    s = block_reduce(s, red);
    ss = block_reduce(ss, red);
    if (threadIdx.x == 0) {
      float m = s / (float)len;
      float var = fmaxf(ss / (float)len - m * m, 0.f);
      g_m[n] = m;
      g_rs[n] = 1.f / (sqrtf(var) + 1e-8f);
    }
    __syncthreads();
  }
}

__device__ void standardize(const float *in, float *out, int len) {
  for (int i = blockIdx.x * NTHR + threadIdx.x; i < 4 * len; i += GSZ) {
    int n = i / len;
    out[i] = (in[i] - g_m[n]) * g_rs[n];
  }
}

__device__ void conv5x5(const float *__restrict__ in, const float *__restrict__ w,
                        const float *__restrict__ bias, float *__restrict__ out,
                        int Cin, int Cout, int HW, bool do_relu) {
  int npix = HW * HW;
  const int NJOB = 4 * Cout * npix;
  CHUNK_LOOP(NJOB) {
    int x = idx % HW;
    int t = idx / HW;
    int y = t % HW;
    t /= HW;
    int f = t % Cout;
    int n = t / Cout;
    float acc = bias ? bias[f] : 0.f;
    const float *wb = w + f * Cin * 25;
    for (int c = 0; c < Cin; ++c) {
      const float *ib = in + (n * Cin + c) * npix;
      const float *wc = wb + c * 25;
#pragma unroll
      for (int ky = 0; ky < 5; ++ky) {
        int yy = y + ky - 2;
        if ((unsigned)yy >= (unsigned)HW) continue;
#pragma unroll
        for (int kx = 0; kx < 5; ++kx) {
          int xx = x + kx - 2;
          if ((unsigned)xx >= (unsigned)HW) continue;
          acc += ib[yy * HW + xx] * wc[ky * 5 + kx];
        }
      }
    }
    out[idx] = do_relu ? fmaxf(acc, 0.f) : acc;
  }
}

__device__ void maxpool2(const float *__restrict__ in, float *__restrict__ out,
                         int C, int H) {
  int Ho = H / 2;
  int N = 4 * C * Ho * Ho;
  for (int idx = blockIdx.x * NTHR + threadIdx.x; idx < N; idx += GSZ) {
    int xo = idx % Ho;
    int t = idx / Ho;
    int yo = t % Ho;
    t /= Ho;
    const float *ib = in + t * H * H + (yo * 2) * H + xo * 2;
    out[idx] = fmaxf(fmaxf(ib[0], ib[1]), fmaxf(ib[H], ib[H + 1]));
  }
}

__device__ void bn_stats(const float *in, int C, int npix, float *red) {
  int cnt = 4 * npix;
  for (int c = blockIdx.x; c < C; c += NBLK) {
    float s = 0.f, ss = 0.f;
    for (int i = threadIdx.x; i < cnt; i += NTHR) {
      int n = i / npix, pp = i % npix;
      float v = in[(n * C + c) * npix + pp];
      s += v;
      ss += v * v;
    }
    s = block_reduce(s, red);
    ss = block_reduce(ss, red);
    if (threadIdx.x == 0) {
      float m = s / (float)cnt;
      float var = fmaxf(ss / (float)cnt - m * m, 0.f);
      g_m[c] = m;
      g_rs[c] = rsqrtf(var + 1e-5f);
    }
    __syncthreads();
  }
}

__device__ void bn_apply(float *buf, int C, int npix, const float *gam, const float *bet) {
  int N = 4 * C * npix;
  for (int i = blockIdx.x * NTHR + threadIdx.x; i < N; i += GSZ) {
    int c = (i / npix) % C;
    buf[i] = (buf[i] - g_m[c]) * g_rs[c] * gam[c] + bet[c];
  }
}

// copy padded code a -> dense [n][F][32][32]
__device__ void unpad(const float *__restrict__ ap, float *__restrict__ dense, int F) {
  int N = 4 * F * 1024;
  for (int i = blockIdx.x * NTHR + threadIdx.x; i < N; i += GSZ) {
    int pix = i & 1023;
    int nf = i >> 10;
    int y = pix >> 5, x = pix & 31;
    dense[i] = ap[nf * 1600 + (y + 4) * 40 + (x + 4)];
  }
}

// ============ LCA2: F=32, C=16 ============
// phaseA: 2 f-partials, 4 c per thread; padded a (no bounds checks).
// jobs (part2, n4, cg4, pixE1296) = 41472
__device__ void lca2_phaseA(const float *__restrict__ ap, float *__restrict__ recon,
                            const float *__restrict__ swA) {
  const int NJOB = 2 * 4 * 4 * 1296;
  CHUNK_LOOP(NJOB) {
    int pix = idx % 1296;
    int t = idx / 1296;
    int cg = t & 3;
    t >>= 2;
    int n = t & 3;
    int part = t >> 2;
    int Y = pix / 36, X = pix % 36;
    int aoff = (Y + 4) * 40 + (X + 4);
    ull acc01 = 0, acc23 = 0;
    const float *ab = ap + (n * 32 + part * 16) * 1600 + aoff;
    const ulonglong2 *wv = (const ulonglong2 *)(swA + part * 6400) + cg;  // [f][tap][16c]
    for (int ff = 0; ff < 16; ++ff) {
      const float *af = ab + ff * 1600;
      const ulonglong2 *wf = wv + ff * 100;
#pragma unroll
      for (int ky = 0; ky < 5; ++ky) {
#pragma unroll
        for (int kx = 0; kx < 5; ++kx) {
          float av = af[-(ky * 40 + kx)];
          ull av2 = dup2(av);
          ulonglong2 w = wf[(ky * 5 + kx) * 4];
          acc01 = ffma2(av2, w.x, acc01);
          acc23 = ffma2(av2, w.y, acc23);
        }
      }
    }
    float c0, c1, c2, c3;
    unpack2(acc01, c0, c1);
    unpack2(acc23, c2, c3);
    float *rb = recon + ((n * 16 + cg * 4) * 1296 + pix) * 2 + part;
    rb[0] = c0;
    rb[2592] = c1;
    rb[5184] = c2;
    rb[7776] = c3;
  }
}

// phaseB: fg=4. jobs (n4, g8, pix1024) = 32768
__device__ void lca2_phaseB(float *__restrict__ u, float *__restrict__ ap,
                            const float *__restrict__ recon,
                            const float *__restrict__ drive,
                            const float *__restrict__ swB) {
  const int NJOB = 4 * 8 * 1024;
  CHUNK_LOOP(NJOB) {
    int pix = idx & 1023;
    int t = idx >> 10;
    int g = t & 7, n = t >> 3;
    int y = pix >> 5, x = pix & 31;
    ull acc01 = 0, acc23 = 0;
    const float *rb = recon + n * 16 * 2592;                  // [c][1296][2]
    const ulonglong2 *wv = (const ulonglong2 *)swB + g;       // [c][tap][32f]
    for (int c = 0; c < 16; ++c) {
      const float *rc = rb + c * 2592;
      const ulonglong2 *wc = wv + c * 200;
#pragma unroll
      for (int ky = 0; ky < 5; ++ky) {
        const float2 *rrow = (const float2 *)(rc + ((y + ky) * 36 + x) * 2);
#pragma unroll
        for (int kx = 0; kx < 5; ++kx) {
          float2 r2 = rrow[kx];
          ull rv2 = dup2(r2.x + r2.y);
          ulonglong2 w = wc[(ky * 5 + kx) * 8];
          acc01 = ffma2(rv2, w.x, acc01);
          acc23 = ffma2(rv2, w.y, acc23);
        }
      }
    }
    float inh[4];
    unpack2(acc01, inh[0], inh[1]);
    unpack2(acc23, inh[2], inh[3]);
    int f0 = g * 4;
#pragma unroll
    for (int j = 0; j < 4; ++j) {
      int i = (n * 32 + f0 + j) * 1024 + pix;
      float uv = u[i];
      float av = fmaxf(uv - 0.5f, 0.f);
      float un = uv + 0.001f * (drive[i] - uv - inh[j] + av);
      u[i] = un;
      ap[(n * 32 + f0 + j) * 1600 + (y + 4) * 40 + (x + 4)] = fmaxf(un - 0.5f, 0.f);
    }
  }
}

// ============ LCA1: F=16, C=3 (pad 4) ============
// phaseA: 4 f-partials. jobs (part4, n4, pixE) = 20736
__device__ void lca1_phaseA(const float *__restrict__ ap, float *__restrict__ recon,
                            const float *__restrict__ swA) {
  const int NJOB = 4 * 4 * 1296;
  CHUNK_LOOP(NJOB) {
    int pix = idx % 1296;
    int t = idx / 1296;
    int n = t & 3, part = t >> 2;
    int Y = pix / 36, X = pix % 36;
    int aoff = (Y + 4) * 40 + (X + 4);
    ull acc01 = 0, acc23 = 0;
    const float *ab = ap + (n * 16 + part * 4) * 1600 + aoff;
    const ulonglong2 *wv = (const ulonglong2 *)swA + part * 100;  // [f][tap][4c]
    for (int ff = 0; ff < 4; ++ff) {
      const float *af = ab + ff * 1600;
      const ulonglong2 *wf = wv + ff * 25;
#pragma unroll
      for (int ky = 0; ky < 5; ++ky) {
#pragma unroll
        for (int kx = 0; kx < 5; ++kx) {
          float av = af[-(ky * 40 + kx)];
          ull av2 = dup2(av);
          ulonglong2 w = wf[ky * 5 + kx];
          acc01 = ffma2(av2, w.x, acc01);
          acc23 = ffma2(av2, w.y, acc23);
        }
      }
    }
    float c0, c1, c2, c3;
    unpack2(acc01, c0, c1);
    unpack2(acc23, c2, c3);
    float *rbb = recon + (n * 3 * 1296 + pix) * 4 + part;  // [n][3c][1296][4]
    rbb[0] = c0;
    rbb[5184] = c1;
    rbb[10368] = c2;
  }
}

// phaseB: fg=2. jobs (n4, g8, pix1024) = 32768
__device__ void lca1_phaseB(float *__restrict__ u, float *__restrict__ ap,
                            const float *__restrict__ recon,
                            const float *__restrict__ drive,
                            const float *__restrict__ swB) {
  const int NJOB = 4 * 8 * 1024;
  CHUNK_LOOP(NJOB) {
    int pix = idx & 1023;
    int t = idx >> 10;
    int g = t & 7, n = t >> 3;
    int y = pix >> 5, x = pix & 31;
    ull acc01 = 0;
    const float *rb = recon + n * 3 * 5184;  // [c][1296][4]
    const float *wb = swB + g * 2;           // [c][tap][16f]
    for (int c = 0; c < 3; ++c) {
      const float *rc = rb + c * 5184;
      const float *wc = wb + c * 400;
#pragma unroll
      for (int ky = 0; ky < 5; ++ky) {
        const ulonglong2 *rrow = (const ulonglong2 *)(rc + ((y + ky) * 36 + x) * 4);
#pragma unroll
        for (int kx = 0; kx < 5; ++kx) {
          ulonglong2 r4 = rrow[kx];
          ull s = add2(r4.x, r4.y);  // (p0+p2, p1+p3)
          float lo, hi;
          unpack2(s, lo, hi);
          ull rv2 = dup2(lo + hi);
          ull w = *(const ull *)(wc + (ky * 5 + kx) * 16);
          acc01 = ffma2(rv2, w, acc01);
        }
      }
    }
    float inh[2];
    unpack2(acc01, inh[0], inh[1]);
    int f0 = g * 2;
#pragma unroll
    for (int j = 0; j < 2; ++j) {
      int i = (n * 16 + f0 + j) * 1024 + pix;
      float uv = u[i];
      float av = fmaxf(uv - 0.5f, 0.f);
      float un = uv + 0.001f * (drive[i] - uv - inh[j] + av);
      u[i] = un;
      ap[(n * 16 + f0 + j) * 1600 + (y + 4) * 40 + (x + 4)] = fmaxf(un - 0.5f, 0.f);
    }
  }
}

// ---- split-K fully-connected ----
__device__ void fc_partial(const float *__restrict__ in, const float *__restrict__ w,
                           float *__restrict__ part, int K, int J, int KP) {
  int kw = K / KP;
  const int NJOB = 4 * J * KP;
  CHUNK_LOOP(NJOB) {
    int kp = idx % KP;
    int t = idx / KP;
    int j = t % J, n = t / J;
    const float *ir = in + n * K + kp * kw;
    const float *wr = w + j * K + kp * kw;
    float acc = 0.f;
    for (int k = 0; k < kw; ++k) acc += ir[k] * wr[k];
    part[idx] = acc;
  }
}

__device__ void fc_reduce(const float *__restrict__ part, const float *__restrict__ bias,
                          float *__restrict__ out, int J, int KP, bool do_relu) {
  const int NJOB = 4 * J;
  for (int idx = blockIdx.x * NTHR + threadIdx.x; idx < NJOB; idx += GSZ) {
    float acc = bias[idx % J];
    for (int kp = 0; kp < KP; ++kp) acc += part[idx * KP + kp];
    out[idx] = do_relu ? fmaxf(acc, 0.f) : acc;
  }
}

// ===================== the whole network, one persistent kernel =====================
__global__ void __launch_bounds__(NTHR, 1) splitnn_kernel(P p) {
  extern __shared__ float smem[];
  float *swA = smem + SW_A;
  float *swB = smem + SW_B;
  float *red = smem + RED_OFF;

  // ---- stage LCA1 weights: swA1 [f][tap][4c], swB1 [c][tap][16f] ----
  for (int i = threadIdx.x; i < 1600; i += NTHR) {
    int f = i / 100, r = i % 100, tap = r >> 2, c = r & 3;
    swA[i] = (c < 3) ? p.w1[(f * 3 + c) * 25 + tap] : 0.f;
  }
  for (int i = threadIdx.x; i < 1200; i += NTHR) {
    int c = i / 400, r = i % 400, tap = r >> 4, f = r & 15;
    swB[i] = p.w1[(f * 3 + c) * 25 + tap];
  }

  // ---- standardize input, drive1, u=a=0 ----
  sample_stats(p.x, 3072, red);
  grid_sync();
  standardize(p.x, g_xs, 3072);
  zero_buf(g_u, 65536);
  zero_buf(g_a, 102400);  // padded a for F=16 (incl. zero border)
  grid_sync();
  conv5x5(g_xs, p.w1, nullptr, g_drive, 3, 16, 32, false);
  grid_sync();

  // ---- LCA1 ----
  for (int it = 0; it < 500; ++it) {
    lca1_phaseA(g_a, g_recon, swA);
    grid_sync();
    lca1_phaseB(g_u, g_a, g_recon, g_drive, swB);
    grid_sync();
  }
  unpad(g_a, g_h, 16);
  grid_sync();
  bn_stats(g_h, 16, 1024, red);
  grid_sync();
  bn_apply(g_h, 16, 1024, p.bn1g, p.bn1b);
  grid_sync();

  // ---- stage LCA2 weights, standardize, drive2 ----
  sample_stats(g_h, 16384, red);
  grid_sync();
  standardize(g_h, g_xs, 16384);
  grid_sync();
  conv5x5(g_xs, p.w2, nullptr, g_drive, 16, 32, 32, false);
  zero_buf(g_u, 131072);
  zero_buf(g_a, 204800);  // padded a for F=32
  for (int i = threadIdx.x; i < 12800; i += NTHR) {
    int f = i / 400, r = i % 400, tap = r >> 4, c = r & 15;
    swA[i] = p.w2[(f * 16 + c) * 25 + tap];
  }
  for (int i = threadIdx.x; i < 12800; i += NTHR) {
    int c = i / 800, r = i % 800, tap = r >> 5, f = r & 31;
    swB[i] = p.w2[(f * 16 + c) * 25 + tap];
  }
  grid_sync();

  // ---- LCA2 ----
  for (int it = 0; it < 500; ++it) {
    lca2_phaseA(g_a, g_recon, swA);
    grid_sync();
    lca2_phaseB(g_u, g_a, g_recon, g_drive, swB);
    grid_sync();
  }
  unpad(g_a, g_h, 32);
  grid_sync();
  maxpool2(g_h, g_xs, 32, 32);
  grid_sync();
  bn_stats(g_xs, 32, 256, red);
  grid_sync();
  bn_apply(g_xs, 32, 256, p.bn2g, p.bn2b);
  grid_sync();

  // ---- conv tail ----
  conv5x5(g_xs, p.wc1, p.bc1, g_h, 32, 64, 16, true);
  grid_sync();
  maxpool2(g_h, g_drive, 64, 16);
  grid_sync();
  bn_stats(g_drive, 64, 64, red);
  grid_sync();
  bn_apply(g_drive, 64, 64, p.bn3g, p.bn3b);
  grid_sync();
  conv5x5(g_drive, p.wc2, p.bc2, g_h, 64, 128, 8, true);
  grid_sync();
  maxpool2(g_h, g_xs, 128, 8);
  grid_sync();
  bn_stats(g_xs, 128, 16, red);
  grid_sync();
  bn_apply(g_xs, 128, 16, p.bn4g, p.bn4b);
  grid_sync();
  conv5x5(g_xs, p.wc3, p.bc3, g_h, 128, 256, 4, true);
  grid_sync();
  maxpool2(g_h, g_drive, 256, 4);  // [4,256,2,2] == flat [4,1024]
  grid_sync();
  bn_stats(g_drive, 256, 4, red);
  grid_sync();
  bn_apply(g_drive, 256, 4, p.bn5g, p.bn5b);
  grid_sync();

  // ---- classifier (split-K) ----
  fc_partial(g_drive, p.wf1, g_fcp, 1024, 512, 8);
  grid_sync();
  fc_reduce(g_fcp, p.bf1, g_fc, 512, 8, true);
  grid_sync();
  fc_partial(g_fc, p.wf2, g_fcp, 512, 10, 8);
  grid_sync();
  fc_reduce(g_fcp, p.bf2, p.out, 10, 8, false);
}

extern "C" void kernel_launch(void *const *d_in, const int *in_sizes, int n_in,
                              void *d_out, int out_size) {
  (void)in_sizes;
  (void)n_in;
  (void)out_size;
  P p;
  p.x = (const float *)d_in[0];
  p.w1 = (const float *)d_in[1];
  p.w2 = (const float *)d_in[2];
  p.bn1g = (const float *)d_in[3];
  p.bn1b = (const float *)d_in[4];
  p.bn2g = (const float *)d_in[5];
  p.bn2b = (const float *)d_in[6];
  p.wc1 = (const float *)d_in[7];
  p.bc1 = (const float *)d_in[8];
  p.bn3g = (const float *)d_in[9];
  p.bn3b = (const float *)d_in[10];
  p.wc2 = (const float *)d_in[11];
  p.bc2 = (const float *)d_in[12];
  p.bn4g = (const float *)d_in[13];
  p.bn4b = (const float *)d_in[14];
  p.wc3 = (const float *)d_in[15];
  p.bc3 = (const float *)d_in[16];
  p.bn5g = (const float *)d_in[17];
  p.bn5b = (const float *)d_in[18];
  p.wf1 = (const float *)d_in[19];
  p.bf1 = (const float *)d_in[20];
  p.wf2 = (const float *)d_in[21];
  p.bf2 = (const float *)d_in[22];
  p.out = (float *)d_out;

  cudaFuncSetAttribute(reinterpret_cast<const void *>(splitnn_kernel),
                       cudaFuncAttributeMaxDynamicSharedMemorySize, SMEM_BYTES);
  splitnn_kernel<<<NBLK, NTHR, SMEM_BYTES>>>(p);
}